// round 9
// baseline (speedup 1.0000x reference)
#include <cuda_runtime.h>
#include <cstdint>

#define BB 4
#define CC 32
#define PP 65536
#define KK 256
#define WIN 2048
#define NWIN (PP / WIN)            // 32
#define GRID2 (BB * NWIN)          // 128
#define T2 512
#define TROW 36                    // row stride (floats) for T3 and g_fsum

// Global scratch (static device arrays -> allowed). ~45 MB.
__device__ float g_Ft[(size_t)BB * PP * 32];   // [b][p][c]  pixel-major features
__device__ float g_At[(size_t)BB * PP * 12];   // [b][p][j]  pixel-major weights (9 + 3 pad)
__device__ __align__(16) float g_fsum[BB * KK * TROW];  // [b][t][c<32], wsum at 32
__device__ unsigned g_done;

// ---------------- pass 1: transpose feats + assoc to pixel-major ----------------
__global__ __launch_bounds__(256)
void transpose_k(const float* __restrict__ feats, const float* __restrict__ assoc) {
    __shared__ float sf[32][257];
    __shared__ float sa[9][257];
    const int b    = blockIdx.x >> 8;          // 256 tiles of 256 px per image
    const int p0   = (blockIdx.x & 255) << 8;
    const int t    = threadIdx.x;

    const float* fb = feats + (size_t)b * 32 * PP + p0 + t;
#pragma unroll
    for (int c = 0; c < 32; c++) sf[c][t] = fb[(size_t)c * PP];
    const float* ab = assoc + (size_t)b * 9 * PP + p0 + t;
#pragma unroll
    for (int j = 0; j < 9; j++) sa[j][t] = ab[(size_t)j * PP];
    __syncthreads();

    float* Fo = g_Ft + ((size_t)b * PP + p0) * 32;
#pragma unroll
    for (int k = 0; k < 32; k++) {             // linear coalesced STG; conflict-free LDS
        const int o = t + k * 256;
        Fo[o] = sf[o & 31][o >> 5];
    }
    float4* Ao = (float4*)(g_At + ((size_t)b * PP + p0) * 12);
    Ao[t * 3 + 0] = make_float4(sa[0][t], sa[1][t], sa[2][t], sa[3][t]);
    Ao[t * 3 + 1] = make_float4(sa[4][t], sa[5][t], sa[6][t], sa[7][t]);
    Ao[t * 3 + 2] = make_float4(sa[8][t], 0.f, 0.f, 0.f);
}

// ---------------- pass 2: sort by bin, 9-FMA-per-pixel gather ----------------
// smem: T3[3][256][TROW] | plist[WIN] | cnt[256] | offs[257]
#define T3_F   (3 * KK * TROW)                 // 27648 floats
#define SMEM2  ((T3_F + WIN + KK + KK + 1) * 4)

__global__ __launch_bounds__(T2)
void gather_k(const int* __restrict__ idxmap, float* __restrict__ out) {
    extern __shared__ float sm[];
    float* T3   = sm;                          // [3][256][TROW]
    int* plist  = (int*)(sm + T3_F);           // [WIN]
    int* cnt    = plist + WIN;                 // [256]
    int* offs   = cnt + KK;                    // [257]

    const int b    = blockIdx.x >> 5;
    const int s    = blockIdx.x & 31;
    const int p0   = s * WIN;
    const int tid  = threadIdx.x;
    const int wid  = tid >> 5;
    const int lane = tid & 31;

    for (int i = tid; i < T3_F / 4; i += T2)
        ((float4*)T3)[i] = make_float4(0.f, 0.f, 0.f, 0.f);
    if (tid < KK) cnt[tid] = 0;
    __syncthreads();

    // ---- count (4 px / thread) ----
    int idxv[4];
#pragma unroll
    for (int k = 0; k < 4; k++) {
        idxv[k] = idxmap[(size_t)b * PP + p0 + tid + k * T2];
        atomicAdd(&cnt[idxv[k]], 1);
    }
    __syncthreads();

    // ---- exclusive scan of 256 counts (warp 0) ----
    if (wid == 0) {
        int running = 0;
        for (int g = 0; g < KK / 32; g++) {
            const int v = cnt[g * 32 + lane];
            int incl = v;
#pragma unroll
            for (int d = 1; d < 32; d <<= 1) {
                int n = __shfl_up_sync(0xffffffffu, incl, d);
                if (lane >= d) incl += n;
            }
            offs[g * 32 + lane] = running + incl - v;
            running += __shfl_sync(0xffffffffu, incl, 31);
        }
        if (lane == 0) offs[KK] = WIN;
    }
    __syncthreads();
    if (tid < KK) cnt[tid] = offs[tid];        // cursors
    __syncthreads();
#pragma unroll
    for (int k = 0; k < 4; k++)
        plist[atomicAdd(&cnt[idxv[k]], 1)] = tid + k * T2;
    __syncthreads();

    // ---- gather: warp = source bin row iy=wid; each pixel visited ONCE ----
    const float*  Fb = g_Ft + ((size_t)b * PP + p0) * 32;
    const float4* Ab = (const float4*)(g_At + ((size_t)b * PP + p0) * 12);

    for (int kx = 0; kx < 16; kx++) {
        float acc[9], aw[9];
#pragma unroll
        for (int j = 0; j < 9; j++) { acc[j] = 0.f; aw[j] = 0.f; }

        const int beg = offs[wid * 16 + kx];
        const int end = offs[wid * 16 + kx + 1];
        for (int e = beg; e < end; e++) {
            const int pl = plist[e];                         // LDS broadcast
            const float  f  = Fb[pl * 32 + lane];            // 128-B line, coalesced
            const float4 w0 = Ab[pl * 3 + 0];                // broadcast LDG.128 x3
            const float4 w1 = Ab[pl * 3 + 1];
            const float4 w2 = Ab[pl * 3 + 2];
            acc[0] += w0.x * f; aw[0] += w0.x;
            acc[1] += w0.y * f; aw[1] += w0.y;
            acc[2] += w0.z * f; aw[2] += w0.z;
            acc[3] += w0.w * f; aw[3] += w0.w;
            acc[4] += w1.x * f; aw[4] += w1.x;
            acc[5] += w1.y * f; aw[5] += w1.y;
            acc[6] += w1.z * f; aw[6] += w1.z;
            acc[7] += w1.w * f; aw[7] += w1.w;
            acc[8] += w2.x * f; aw[8] += w2.x;
        }

        // ---- race-free deposit: buffer d=dy+1, target row wid+dy has unique writer ----
#pragma unroll
        for (int dy = -1; dy <= 1; dy++) {
            const int r = wid + dy;
            if (r < 0 || r > 15) continue;
            const int d = dy + 1;
#pragma unroll
            for (int dx = -1; dx <= 1; dx++) {
                const int x = kx + dx;
                if (x < 0 || x > 15) continue;
                const int j = d * 3 + dx + 1;
                float* row = T3 + (size_t)(d * KK + r * 16 + x) * TROW;
                row[lane] += acc[j];                        // exclusive: no atomics
                if (lane == 0) row[32] += aw[j];
            }
        }
    }
    __syncthreads();

    // ---- CTA reduce over 3 buffers + scalar REDG to global ----
    {
        float* gf = g_fsum + (size_t)b * KK * TROW;
        for (int i = tid; i < KK * TROW / 4; i += T2) {
            const float4 a = ((float4*)T3)[i];
            const float4 q = ((float4*)T3)[i + KK * TROW / 4];
            const float4 c = ((float4*)T3)[i + 2 * (KK * TROW / 4)];
            const float vx = a.x + q.x + c.x, vy = a.y + q.y + c.y;
            const float vz = a.z + q.z + c.z, vw = a.w + q.w + c.w;
            atomicAdd(gf + 4 * i + 0, vx);
            atomicAdd(gf + 4 * i + 1, vy);
            atomicAdd(gf + 4 * i + 2, vz);
            atomicAdd(gf + 4 * i + 3, vw);
        }
    }

    // ---- fused epilogue: last CTA normalizes, writes out, re-zeroes scratch ----
    __shared__ unsigned s_rank;
    __threadfence();
    __syncthreads();
    if (tid == 0) s_rank = atomicAdd(&g_done, 1u);
    __syncthreads();
    if (s_rank == GRID2 - 1) {
        __threadfence();
        for (int i = tid; i < BB * KK * CC; i += T2) {
            const int c  = i & 31;
            const int bk = i >> 5;
            const float ws = g_fsum[(size_t)bk * TROW + 32];
            const float fs = g_fsum[(size_t)bk * TROW + c];
            const int k = bk & 255, bb2 = bk >> 8;
            out[((size_t)(bb2 * CC) + c) * KK + k] = (ws > 1e-16f) ? fs / ws : 0.f;
        }
        __syncthreads();
        for (int i = tid; i < BB * KK * TROW; i += T2) g_fsum[i] = 0.f;
        if (tid == 0) g_done = 0;
    }
}

extern "C" void kernel_launch(void* const* d_in, const int* in_sizes, int n_in,
                              void* d_out, int out_size) {
    const float* feats  = (const float*)d_in[0];
    const float* assoc  = (const float*)d_in[1];
    const int*   idxmap = (const int*)d_in[2];

    static int configured = 0;
    if (!configured) {
        cudaFuncSetAttribute(gather_k, cudaFuncAttributeMaxDynamicSharedMemorySize,
                             SMEM2);
        configured = 1;
    }
    transpose_k<<<BB * 256, 256>>>(feats, assoc);
    gather_k<<<GRID2, T2, SMEM2>>>(idxmap, (float*)d_out);
}

// round 10
// speedup vs baseline: 1.3447x; 1.3447x over previous
#include <cuda_runtime.h>
#include <cstdint>

#define BB 4
#define CC 32
#define PP 65536
#define KK 256
#define PCH 512
#define CHUNKS 4
#define WINPX (PCH * CHUNKS)         // 2048
#define NWIN (PP / WINPX)            // 32
#define GRID (BB * NWIN)             // 128
#define THREADS 512
#define NWARPS 16
#define TROW 36                      // T3/g_fsum row stride in floats

// smem (floats): F[512*32] | A[512*12] | T3[3*256*36] | plist[512] | cnt[256] | offs[257]
#define F_F    (PCH * 32)            // 16384
#define A_F    (PCH * 12)            // 6144
#define T3_F   (3 * KK * TROW)       // 27648
#define SMEM_FLOATS (F_F + A_F + T3_F + PCH + KK + KK + 1)
#define SMEM_BYTES  (SMEM_FLOATS * 4)   // ~204.8 KB -> 1 CTA/SM

__device__ __align__(16) float g_fsum[BB * KK * TROW];  // [b][k][c<32], wsum@32; zero at load
__device__ unsigned g_done;

__global__ __launch_bounds__(THREADS)
void spix_main(const float* __restrict__ feats,
               const float* __restrict__ assoc,
               const int*   __restrict__ idxmap,
               float* __restrict__ out) {
    extern __shared__ float sm[];
    float* F_sh  = sm;                        // [512][32] pixel-major
    float* A_sh  = sm + F_F;                  // [512][12] (9 weights + pad)
    float* T3    = A_sh + A_F;                // [3][256][36]
    int*   plist = (int*)(T3 + T3_F);         // [512] pixel ids sorted by base bin
    int*   cnt   = plist + PCH;               // [256]
    int*   offs  = cnt + KK;                  // [257]

    const int b    = blockIdx.x >> 5;
    const int s    = blockIdx.x & 31;
    const int tid  = threadIdx.x;
    const int wid  = tid >> 5;
    const int lane = tid & 31;

    // zero persistent T3 once
    for (int i = tid; i < T3_F / 4; i += THREADS)
        ((float4*)T3)[i] = make_float4(0.f, 0.f, 0.f, 0.f);

    for (int ch = 0; ch < CHUNKS; ch++) {
        const int p0 = s * WINPX + ch * PCH;

        if (tid < KK) cnt[tid] = 0;
        __syncthreads();   // protects: cnt zero vs counts; plist/F/A reuse vs prev gather

        // ---- stage F: thread = pixel; 32 coalesced LDG.32 -> 8 STS.128 ----
        {
            const float* src = feats + (size_t)b * CC * PP + p0 + tid;
            float4* dst = (float4*)(F_sh + tid * 32);
#pragma unroll
            for (int q = 0; q < 8; q++) {
                float4 v;
                v.x = src[(size_t)(4 * q + 0) * PP];
                v.y = src[(size_t)(4 * q + 1) * PP];
                v.z = src[(size_t)(4 * q + 2) * PP];
                v.w = src[(size_t)(4 * q + 3) * PP];
                dst[q] = v;
            }
        }
        // ---- stage A: thread = pixel; 9 coalesced LDG.32 -> 3 STS.128 ----
        {
            const float* src = assoc + (size_t)b * 9 * PP + p0 + tid;
            float4* dst = (float4*)(A_sh + tid * 12);
            float w[9];
#pragma unroll
            for (int j = 0; j < 9; j++) w[j] = src[(size_t)j * PP];
            dst[0] = make_float4(w[0], w[1], w[2], w[3]);
            dst[1] = make_float4(w[4], w[5], w[6], w[7]);
            dst[2] = make_float4(w[8], 0.f, 0.f, 0.f);
        }

        // ---- count pixels per base bin (1 cheap shared atomic / px) ----
        const int idxA = idxmap[(size_t)b * PP + p0 + tid];
        atomicAdd(&cnt[idxA], 1);
        __syncthreads();

        // ---- exclusive scan of 256 counts (warp 0) ----
        if (wid == 0) {
            int running = 0;
            for (int g = 0; g < KK / 32; g++) {
                const int v = cnt[g * 32 + lane];
                int incl = v;
#pragma unroll
                for (int d = 1; d < 32; d <<= 1) {
                    int n = __shfl_up_sync(0xffffffffu, incl, d);
                    if (lane >= d) incl += n;
                }
                offs[g * 32 + lane] = running + incl - v;
                running += __shfl_sync(0xffffffffu, incl, 31);
            }
            if (lane == 0) offs[KK] = PCH;
        }
        __syncthreads();
        if (tid < KK) cnt[tid] = offs[tid];    // cursors
        __syncthreads();
        plist[atomicAdd(&cnt[idxA], 1)] = tid;
        __syncthreads();

        // ---- gather: warp = source row iy=wid; each pixel visited ONCE (9 FMAs) ----
        for (int kx = 0; kx < 16; kx++) {
            float acc[9], aw[9];
#pragma unroll
            for (int j = 0; j < 9; j++) { acc[j] = 0.f; aw[j] = 0.f; }

            const int beg = offs[wid * 16 + kx];
            const int end = offs[wid * 16 + kx + 1];
            for (int e = beg; e < end; e++) {
                const int pl = plist[e];                          // LDS broadcast
                const float  f  = F_sh[pl * 32 + lane];           // conflict-free LDS.32
                const float4 w0 = ((const float4*)(A_sh + pl * 12))[0];  // broadcast LDS.128
                const float4 w1 = ((const float4*)(A_sh + pl * 12))[1];
                const float4 w2 = ((const float4*)(A_sh + pl * 12))[2];
                acc[0] += w0.x * f; aw[0] += w0.x;
                acc[1] += w0.y * f; aw[1] += w0.y;
                acc[2] += w0.z * f; aw[2] += w0.z;
                acc[3] += w0.w * f; aw[3] += w0.w;
                acc[4] += w1.x * f; aw[4] += w1.x;
                acc[5] += w1.y * f; aw[5] += w1.y;
                acc[6] += w1.z * f; aw[6] += w1.z;
                acc[7] += w1.w * f; aw[7] += w1.w;
                acc[8] += w2.x * f; aw[8] += w2.x;
            }

            // ---- race-free deposit: buffer dy+1, row r=wid+dy has unique writer warp ----
#pragma unroll
            for (int dy = -1; dy <= 1; dy++) {
                const int r = wid + dy;
                if (r < 0 || r > 15) continue;
                float* buf = T3 + (size_t)((dy + 1) * KK + r * 16) * TROW;
#pragma unroll
                for (int dx = -1; dx <= 1; dx++) {
                    const int x = kx + dx;
                    if (x < 0 || x > 15) continue;
                    const int j = (dy + 1) * 3 + (dx + 1);
                    float* row = buf + x * TROW;
                    row[lane] += acc[j];            // exclusive writer -> plain RMW
                    if (lane == 0) row[32] += aw[j];
                }
            }
        }
        // no sync needed here: each (buffer,row) has one writer for the whole kernel;
        // loop-top __syncthreads fences plist/F/A reuse.
    }
    __syncthreads();

    // ---- reduce 3 buffers + REDG flush (8.4K lanes/CTA) ----
    {
        float* gf = g_fsum + (size_t)b * KK * TROW;
        for (int i = tid; i < KK * TROW; i += THREADS) {
            const float v = T3[i] + T3[i + T3_F / 3] + T3[i + 2 * (T3_F / 3)];
            atomicAdd(gf + i, v);    // pad cols add 0.0 -> harmless
        }
    }

    // ---- fused epilogue: last CTA normalizes, writes out, re-zeroes scratch ----
    __shared__ unsigned s_rank;
    __threadfence();
    __syncthreads();
    if (tid == 0) s_rank = atomicAdd(&g_done, 1u);
    __syncthreads();
    if (s_rank == GRID - 1) {
        __threadfence();
        for (int i = tid; i < BB * KK * CC; i += THREADS) {
            const int c  = i & 31;
            const int bk = i >> 5;
            const float ws = g_fsum[(size_t)bk * TROW + 32];
            const float fs = g_fsum[(size_t)bk * TROW + c];
            const int k = bk & 255, bb2 = bk >> 8;
            out[((size_t)(bb2 * CC) + c) * KK + k] = (ws > 1e-16f) ? fs / ws : 0.f;
        }
        __syncthreads();
        for (int i = tid; i < BB * KK * TROW; i += THREADS) g_fsum[i] = 0.f;
        if (tid == 0) g_done = 0;
    }
}

extern "C" void kernel_launch(void* const* d_in, const int* in_sizes, int n_in,
                              void* d_out, int out_size) {
    const float* feats  = (const float*)d_in[0];
    const float* assoc  = (const float*)d_in[1];
    const int*   idxmap = (const int*)d_in[2];

    static int configured = 0;
    if (!configured) {
        cudaFuncSetAttribute(spix_main, cudaFuncAttributeMaxDynamicSharedMemorySize,
                             SMEM_BYTES);
        configured = 1;
    }
    spix_main<<<GRID, THREADS, SMEM_BYTES>>>(feats, assoc, idxmap, (float*)d_out);
}

// round 11
// speedup vs baseline: 1.7210x; 1.2799x over previous
#include <cuda_runtime.h>
#include <cstdint>

#define BB 4
#define CC 32
#define PP 65536
#define KK 256
#define PCH 512
#define CHUNKS 4
#define WINPX (PCH * CHUNKS)         // 2048
#define NWIN (PP / WINPX)            // 32
#define GRID (BB * NWIN)             // 128
#define THREADS 512
#define FSR 36                       // F row stride (floats): conflict-free STS.128 + LDS
#define TROW 36

#define F_F    (PCH * FSR)           // 18432
#define A_F    (PCH * 12)            // 6144
#define T3_F   (3 * KK * TROW)       // 27648
#define SMEM_FLOATS (F_F + A_F + T3_F + PCH + KK + KK + 1)
#define SMEM_BYTES  (SMEM_FLOATS * 4)   // ~208 KB -> 1 CTA/SM

__device__ __align__(16) float g_fsum[BB * KK * TROW];  // [b][k][c<32], wsum@32; zero at load
__device__ unsigned g_done;

__global__ __launch_bounds__(THREADS)
void spix_main(const float* __restrict__ feats,
               const float* __restrict__ assoc,
               const int*   __restrict__ idxmap,
               float* __restrict__ out) {
    extern __shared__ float sm[];
    float* F_sh  = sm;                        // [512][36] pixel-major (32 used)
    float* A_sh  = sm + F_F;                  // [512][12] (9 weights + pad)
    float* T3    = A_sh + A_F;                // [3][256][36]
    int*   plist = (int*)(T3 + T3_F);         // [512]
    int*   cnt   = plist + PCH;               // [256]
    int*   offs  = cnt + KK;                  // [257]

    const int b    = blockIdx.x >> 5;
    const int s    = blockIdx.x & 31;
    const int tid  = threadIdx.x;
    const int wid  = tid >> 5;
    const int lane = tid & 31;

    for (int i = tid; i < T3_F / 4; i += THREADS)
        ((float4*)T3)[i] = make_float4(0.f, 0.f, 0.f, 0.f);

    for (int ch = 0; ch < CHUNKS; ch++) {
        const int p0 = s * WINPX + ch * PCH;

        if (tid < KK) cnt[tid] = 0;
        __syncthreads();   // fences prev-chunk gather before F/A/plist reuse

        // ---- stage F: thread = pixel; coalesced LDG.32 -> conflict-free STS.128 ----
        {
            const float* src = feats + (size_t)b * CC * PP + p0 + tid;
            float4* dst = (float4*)(F_sh + tid * FSR);
#pragma unroll
            for (int q = 0; q < 8; q++) {
                float4 v;
                v.x = src[(size_t)(4 * q + 0) * PP];
                v.y = src[(size_t)(4 * q + 1) * PP];
                v.z = src[(size_t)(4 * q + 2) * PP];
                v.w = src[(size_t)(4 * q + 3) * PP];
                dst[q] = v;
            }
        }
        // ---- stage A: thread = pixel; 9 LDG.32 -> 3 STS.128 (48B stride: conflict-free) ----
        {
            const float* src = assoc + (size_t)b * 9 * PP + p0 + tid;
            float4* dst = (float4*)(A_sh + tid * 12);
            float w[9];
#pragma unroll
            for (int j = 0; j < 9; j++) w[j] = src[(size_t)j * PP];
            dst[0] = make_float4(w[0], w[1], w[2], w[3]);
            dst[1] = make_float4(w[4], w[5], w[6], w[7]);
            dst[2] = make_float4(w[8], 0.f, 0.f, 0.f);
        }

        // ---- count / scan / place (cheap base-bin counting sort) ----
        const int idxA = idxmap[(size_t)b * PP + p0 + tid];
        atomicAdd(&cnt[idxA], 1);
        __syncthreads();

        if (wid == 0) {
            int running = 0;
            for (int g = 0; g < KK / 32; g++) {
                const int v = cnt[g * 32 + lane];
                int incl = v;
#pragma unroll
                for (int d = 1; d < 32; d <<= 1) {
                    int n = __shfl_up_sync(0xffffffffu, incl, d);
                    if (lane >= d) incl += n;
                }
                offs[g * 32 + lane] = running + incl - v;
                running += __shfl_sync(0xffffffffu, incl, 31);
            }
            if (lane == 0) offs[KK] = PCH;
        }
        __syncthreads();
        if (tid < KK) cnt[tid] = offs[tid];
        __syncthreads();
        plist[atomicAdd(&cnt[idxA], 1)] = tid;
        __syncthreads();

        // ---- gather: warp = source row wid; pixel visited ONCE; rolling deposit ----
        float pend0[3], pend1[3], pw0[3], pw1[3];
#pragma unroll
        for (int d = 0; d < 3; d++) { pend0[d] = pend1[d] = pw0[d] = pw1[d] = 0.f; }

        for (int kx = 0; kx < 16; kx++) {
            float acc[9], aw[9];
#pragma unroll
            for (int j = 0; j < 9; j++) { acc[j] = 0.f; aw[j] = 0.f; }

            const int beg = offs[wid * 16 + kx];
            const int end = offs[wid * 16 + kx + 1];
            for (int e = beg; e < end; e++) {
                const int pl = plist[e];                          // LDS broadcast
                const float  f  = F_sh[pl * FSR + lane];          // conflict-free LDS.32
                const float4 w0 = ((const float4*)(A_sh + pl * 12))[0];  // broadcast LDS.128
                const float4 w1 = ((const float4*)(A_sh + pl * 12))[1];
                const float4 w2 = ((const float4*)(A_sh + pl * 12))[2];
                acc[0] += w0.x * f; aw[0] += w0.x;
                acc[1] += w0.y * f; aw[1] += w0.y;
                acc[2] += w0.z * f; aw[2] += w0.z;
                acc[3] += w0.w * f; aw[3] += w0.w;
                acc[4] += w1.x * f; aw[4] += w1.x;
                acc[5] += w1.y * f; aw[5] += w1.y;
                acc[6] += w1.z * f; aw[6] += w1.z;
                acc[7] += w1.w * f; aw[7] += w1.w;
                acc[8] += w2.x * f; aw[8] += w2.x;
            }

            // rolling-window deposit: 1 RMW per dy per kx (target kx-1 completes now)
#pragma unroll
            for (int d = 0; d < 3; d++) {
                const int r = wid + d - 1;
                if (r < 0 || r > 15) continue;
                const float fl  = pend0[d] + acc[d * 3 + 0];   // + c_{dx=-1}
                const float flw = pw0[d]   + aw[d * 3 + 0];
                if (kx >= 1) {
                    float* row = T3 + (size_t)(d * KK + r * 16 + (kx - 1)) * TROW;
                    row[lane] += fl;                  // exclusive writer: plain RMW
                    if (lane == 0) row[32] += flw;
                }
                pend0[d] = pend1[d] + acc[d * 3 + 1];
                pw0[d]   = pw1[d]   + aw[d * 3 + 1];
                pend1[d] = acc[d * 3 + 2];
                pw1[d]   = aw[d * 3 + 2];
            }
        }
        // flush target x = 15 (pend1 targets x=16: out of range, discard)
#pragma unroll
        for (int d = 0; d < 3; d++) {
            const int r = wid + d - 1;
            if (r < 0 || r > 15) continue;
            float* row = T3 + (size_t)(d * KK + r * 16 + 15) * TROW;
            row[lane] += pend0[d];
            if (lane == 0) row[32] += pw0[d];
        }
    }
    __syncthreads();

    // ---- reduce 3 buffers + REDG flush (8.4K lanes/CTA) ----
    {
        float* gf = g_fsum + (size_t)b * KK * TROW;
        for (int i = tid; i < KK * TROW; i += THREADS) {
            const float v = T3[i] + T3[i + T3_F / 3] + T3[i + 2 * (T3_F / 3)];
            atomicAdd(gf + i, v);
        }
    }

    // ---- fused epilogue: last CTA normalizes, writes out, re-zeroes scratch ----
    __shared__ unsigned s_rank;
    __threadfence();
    __syncthreads();
    if (tid == 0) s_rank = atomicAdd(&g_done, 1u);
    __syncthreads();
    if (s_rank == GRID - 1) {
        __threadfence();
        for (int i = tid; i < BB * KK * CC; i += THREADS) {
            const int c  = i & 31;
            const int bk = i >> 5;
            const float ws = g_fsum[(size_t)bk * TROW + 32];
            const float fs = g_fsum[(size_t)bk * TROW + c];
            const int k = bk & 255, bb2 = bk >> 8;
            out[((size_t)(bb2 * CC) + c) * KK + k] = (ws > 1e-16f) ? fs / ws : 0.f;
        }
        __syncthreads();
        for (int i = tid; i < BB * KK * TROW; i += THREADS) g_fsum[i] = 0.f;
        if (tid == 0) g_done = 0;
    }
}

extern "C" void kernel_launch(void* const* d_in, const int* in_sizes, int n_in,
                              void* d_out, int out_size) {
    const float* feats  = (const float*)d_in[0];
    const float* assoc  = (const float*)d_in[1];
    const int*   idxmap = (const int*)d_in[2];

    static int configured = 0;
    if (!configured) {
        cudaFuncSetAttribute(spix_main, cudaFuncAttributeMaxDynamicSharedMemorySize,
                             SMEM_BYTES);
        configured = 1;
    }
    spix_main<<<GRID, THREADS, SMEM_BYTES>>>(feats, assoc, idxmap, (float*)d_out);
}

// round 12
// speedup vs baseline: 1.9262x; 1.1192x over previous
#include <cuda_runtime.h>
#include <cstdint>

#define BB 4
#define CC 32
#define PP 65536
#define KK 256
#define PCH 1024
#define CHUNKS 2
#define WINPX (PCH * CHUNKS)         // 2048
#define NWIN (PP / WINPX)            // 32
#define GRID (BB * NWIN)             // 128
#define THREADS 1024
#define FSR 36                       // F row stride (floats): conflict-free STS.128 + LDS
#define TROW 36

// smem (floats): F[1024*36] | A3[3*1024*4] | plist int2[1024] | cnt[256] | offs[257]
#define F_F    (PCH * FSR)           // 36864
#define A3_F   (3 * PCH * 4)        // 12288
#define SMEM_FLOATS (F_F + A3_F + 2 * PCH + KK + KK + 1)
#define SMEM_BYTES  (SMEM_FLOATS * 4)   // ~206 KB -> 1 CTA/SM, 32 warps

__device__ __align__(16) float g_fsum[BB * KK * TROW];  // [b][k][c<32], wsum@32; zero at load
__device__ unsigned g_done;

__global__ __launch_bounds__(THREADS, 1)
void spix_main(const float* __restrict__ feats,
               const float* __restrict__ assoc,
               const int*   __restrict__ idxmap,
               float* __restrict__ out) {
    extern __shared__ float sm[];
    float* F_sh  = sm;                        // [1024][36] pixel-major (32 used)
    float* A3    = sm + F_F;                  // [3][1024][4]: A3[d][p][t] = w[3d+t]
    int2*  plist = (int2*)(A3 + A3_F);        // [1024] {mF = 4*pl - ix, pF = 36*pl}
    int*   cnt   = (int*)(plist + PCH);       // [256]
    int*   offs  = cnt + KK;                  // [257]

    const int b    = blockIdx.x >> 5;
    const int s    = blockIdx.x & 31;
    const int tid  = threadIdx.x;
    const int wid  = tid >> 5;
    const int lane = tid & 31;
    const int ky   = wid >> 1;                // target row owned by this warp
    const int par  = wid & 1;                 // kx parity

    // per-warp register accumulators for 8 owned bins, live across all chunks
    float acc[8], aw[8];
#pragma unroll
    for (int i = 0; i < 8; i++) { acc[i] = 0.f; aw[i] = 0.f; }

    const float* F_lane = F_sh + lane;

    for (int ch = 0; ch < CHUNKS; ch++) {
        const int p0 = s * WINPX + ch * PCH;

        if (tid < KK) cnt[tid] = 0;
        __syncthreads();   // fences prev-chunk gather before F/A3/plist reuse

        // ---- stage F: thread = pixel; coalesced LDG.32 -> conflict-free STS.128 ----
        {
            const float* src = feats + (size_t)b * CC * PP + p0 + tid;
            float4* dst = (float4*)(F_sh + tid * FSR);
#pragma unroll
            for (int q = 0; q < 8; q++) {
                float4 v;
                v.x = src[(size_t)(4 * q + 0) * PP];
                v.y = src[(size_t)(4 * q + 1) * PP];
                v.z = src[(size_t)(4 * q + 2) * PP];
                v.w = src[(size_t)(4 * q + 3) * PP];
                dst[q] = v;
            }
        }
        // ---- stage A3: thread = pixel; 9 LDG.32 -> 3 STS.128 (16B stride, conflict-free) ----
        {
            const float* src = assoc + (size_t)b * 9 * PP + p0 + tid;
            float w[9];
#pragma unroll
            for (int j = 0; j < 9; j++) w[j] = src[(size_t)j * PP];
#pragma unroll
            for (int d = 0; d < 3; d++)
                ((float4*)A3)[d * PCH + tid] =
                    make_float4(w[3 * d + 0], w[3 * d + 1], w[3 * d + 2], 0.f);
        }

        // ---- count / scan / place (cheap base-bin counting sort; 1 px/thread) ----
        const int idxA = idxmap[(size_t)b * PP + p0 + tid];
        atomicAdd(&cnt[idxA], 1);
        __syncthreads();

        if (wid == 0) {
            int running = 0;
            for (int g = 0; g < KK / 32; g++) {
                const int v = cnt[g * 32 + lane];
                int incl = v;
#pragma unroll
                for (int d = 1; d < 32; d <<= 1) {
                    int n = __shfl_up_sync(0xffffffffu, incl, d);
                    if (lane >= d) incl += n;
                }
                offs[g * 32 + lane] = running + incl - v;
                running += __shfl_sync(0xffffffffu, incl, 31);
            }
            if (lane == 0) offs[KK] = PCH;
        }
        __syncthreads();
        if (tid < KK) cnt[tid] = offs[tid];    // cursors
        __syncthreads();
        {
            const int slot = atomicAdd(&cnt[idxA], 1);
            plist[slot] = make_int2(4 * tid - (idxA & 15), 36 * tid);
        }
        __syncthreads();

        // ---- gather: warp owns bins (ky, kx = 2*kxi+par); 3 contiguous runs per bin ----
#pragma unroll
        for (int kxi = 0; kxi < 8; kxi++) {
            const int kx = 2 * kxi + par;
            float a = 0.f, w_s = 0.f;
            const int xlo = kx > 0  ? kx - 1 : 0;
            const int xhi = kx < 15 ? kx + 1 : 15;
#pragma unroll
            for (int dy = -1; dy <= 1; dy++) {
                const int sy = ky + dy;
                if (sy < 0 || sy > 15) continue;
                const int d = 1 - dy;              // plane index: dy'=ky-sy => d=dy'+1
                const int beg = offs[sy * 16 + xlo];
                const int end = offs[sy * 16 + xhi + 1];
                // weight elem = d*4096 + 4*pl + (kx-ix+1) = Cw + mF ; always in-bounds
                const float* Aw = A3 + (d * (PCH * 4) + kx + 1);
#pragma unroll 2
                for (int e = beg; e < end; e++) {
                    const int2 pr = plist[e];          // LDS.64 broadcast
                    const float w = Aw[pr.x];          // LDS.32 broadcast
                    const float f = F_lane[pr.y];      // conflict-free LDS.32
                    a   += w * f;
                    w_s += w;
                }
            }
            acc[kxi] += a;
            aw[kxi]  += w_s;
        }
        // no trailing sync needed: loop-top __syncthreads fences reuse
    }

    // ---- flush: fire-and-forget REDG, one shot per owned bin ----
#pragma unroll
    for (int kxi = 0; kxi < 8; kxi++) {
        const int k = ky * 16 + 2 * kxi + par;
        float* gb = &g_fsum[(size_t)(b * KK + k) * TROW];
        atomicAdd(gb + lane, acc[kxi]);
        if (lane == 0) atomicAdd(gb + 32, aw[kxi]);
    }

    // ---- fused epilogue: last CTA normalizes, writes out, re-zeroes scratch ----
    __shared__ unsigned s_rank;
    __threadfence();
    __syncthreads();
    if (tid == 0) s_rank = atomicAdd(&g_done, 1u);
    __syncthreads();
    if (s_rank == GRID - 1) {
        __threadfence();
        for (int i = tid; i < BB * KK * CC; i += THREADS) {
            const int c  = i & 31;
            const int bk = i >> 5;
            const float ws = g_fsum[(size_t)bk * TROW + 32];
            const float fs = g_fsum[(size_t)bk * TROW + c];
            const int k = bk & 255, bb2 = bk >> 8;
            out[((size_t)(bb2 * CC) + c) * KK + k] = (ws > 1e-16f) ? fs / ws : 0.f;
        }
        __syncthreads();
        for (int i = tid; i < BB * KK * TROW; i += THREADS) g_fsum[i] = 0.f;
        if (tid == 0) g_done = 0;
    }
}

extern "C" void kernel_launch(void* const* d_in, const int* in_sizes, int n_in,
                              void* d_out, int out_size) {
    const float* feats  = (const float*)d_in[0];
    const float* assoc  = (const float*)d_in[1];
    const int*   idxmap = (const int*)d_in[2];

    static int configured = 0;
    if (!configured) {
        cudaFuncSetAttribute(spix_main, cudaFuncAttributeMaxDynamicSharedMemorySize,
                             SMEM_BYTES);
        configured = 1;
    }
    spix_main<<<GRID, THREADS, SMEM_BYTES>>>(feats, assoc, idxmap, (float*)d_out);
}

// round 13
// speedup vs baseline: 1.9271x; 1.0005x over previous
#include <cuda_runtime.h>
#include <cstdint>

#define BB 4
#define CC 32
#define PP 65536
#define KK 256
#define PCH 1024
#define CHUNKS 2
#define WINPX (PCH * CHUNKS)         // 2048
#define NWIN (PP / WINPX)            // 32
#define GRID (BB * NWIN)             // 128
#define THREADS 1024
#define FSR 36                       // F row stride (floats): conflict-free STS.128 + LDS
#define TROW 36

// smem (floats): F[1024*36] | A3[3*1024*4] | plist int2[1024] | cnt[256] | offs[257]
#define F_F    (PCH * FSR)           // 36864
#define A3_F   (3 * PCH * 4)         // 12288
#define SMEM_FLOATS (F_F + A3_F + 2 * PCH + KK + KK + 1)
#define SMEM_BYTES  (SMEM_FLOATS * 4)   // ~206 KB -> 1 CTA/SM, 32 warps

__device__ __align__(16) float g_fsum[BB * KK * TROW];  // [b][k][c<32], wsum@32; zero at load
__device__ unsigned g_done;

__global__ __launch_bounds__(THREADS, 1)
void spix_main(const float* __restrict__ feats,
               const float* __restrict__ assoc,
               const int*   __restrict__ idxmap,
               float* __restrict__ out) {
    extern __shared__ float sm[];
    float* F_sh  = sm;                        // [1024][36] pixel-major (32 used)
    float* A3    = sm + F_F;                  // [3][1024][4]: A3[d][p][t] = w[3d+t]
    int2*  plist = (int2*)(A3 + A3_F);        // [1024] {mF = 4*pl - ix, pF = 36*pl}
    int*   cnt   = (int*)(plist + PCH);       // [256]
    int*   offs  = cnt + KK;                  // [257]

    const int b    = blockIdx.x >> 5;
    const int s    = blockIdx.x & 31;
    const int tid  = threadIdx.x;
    const int wid  = tid >> 5;
    const int lane = tid & 31;
    const int ky   = wid >> 1;                // target row owned by this warp
    const int par  = wid & 1;                 // kx parity

    // per-warp register accumulators for 8 owned bins, live across all chunks
    float acc[8], aw[8];
#pragma unroll
    for (int i = 0; i < 8; i++) { acc[i] = 0.f; aw[i] = 0.f; }

    const float* F_lane = F_sh + lane;

    for (int ch = 0; ch < CHUNKS; ch++) {
        const int p0 = s * WINPX + ch * PCH;

        if (tid < KK) cnt[tid] = 0;
        __syncthreads();   // fences prev-chunk gather before F/A3/plist reuse

        // ---- stage F: thread = pixel; coalesced LDG.32 -> conflict-free STS.128 ----
        {
            const float* src = feats + (size_t)b * CC * PP + p0 + tid;
            float4* dst = (float4*)(F_sh + tid * FSR);
#pragma unroll
            for (int q = 0; q < 8; q++) {
                float4 v;
                v.x = src[(size_t)(4 * q + 0) * PP];
                v.y = src[(size_t)(4 * q + 1) * PP];
                v.z = src[(size_t)(4 * q + 2) * PP];
                v.w = src[(size_t)(4 * q + 3) * PP];
                dst[q] = v;
            }
        }
        // ---- stage A3: thread = pixel; 9 LDG.32 -> 3 STS.128 (16B stride, conflict-free) ----
        {
            const float* src = assoc + (size_t)b * 9 * PP + p0 + tid;
            float w[9];
#pragma unroll
            for (int j = 0; j < 9; j++) w[j] = src[(size_t)j * PP];
#pragma unroll
            for (int d = 0; d < 3; d++)
                ((float4*)A3)[d * PCH + tid] =
                    make_float4(w[3 * d + 0], w[3 * d + 1], w[3 * d + 2], 0.f);
        }

        // ---- count / scan / place (cheap base-bin counting sort; 1 px/thread) ----
        const int idxA = idxmap[(size_t)b * PP + p0 + tid];
        atomicAdd(&cnt[idxA], 1);
        __syncthreads();

        if (wid == 0) {
            int running = 0;
            for (int g = 0; g < KK / 32; g++) {
                const int v = cnt[g * 32 + lane];
                int incl = v;
#pragma unroll
                for (int d = 1; d < 32; d <<= 1) {
                    int n = __shfl_up_sync(0xffffffffu, incl, d);
                    if (lane >= d) incl += n;
                }
                offs[g * 32 + lane] = running + incl - v;
                running += __shfl_sync(0xffffffffu, incl, 31);
            }
            if (lane == 0) offs[KK] = PCH;
        }
        __syncthreads();
        if (tid < KK) cnt[tid] = offs[tid];    // cursors
        __syncthreads();
        {
            const int slot = atomicAdd(&cnt[idxA], 1);
            plist[slot] = make_int2(4 * tid - (idxA & 15), 36 * tid);
        }
        __syncthreads();

        // ---- gather: warp owns bins (ky, kx = 2*kxi+par); 3 contiguous runs per bin ----
#pragma unroll
        for (int kxi = 0; kxi < 8; kxi++) {
            const int kx = 2 * kxi + par;
            float a = 0.f, w_s = 0.f;
            const int xlo = kx > 0  ? kx - 1 : 0;
            const int xhi = kx < 15 ? kx + 1 : 15;
#pragma unroll
            for (int dy = -1; dy <= 1; dy++) {
                const int sy = ky + dy;
                if (sy < 0 || sy > 15) continue;
                const int d = 1 - dy;              // plane index: dy'=ky-sy => d=dy'+1
                const int beg = offs[sy * 16 + xlo];
                const int end = offs[sy * 16 + xhi + 1];
                // weight elem = d*4096 + 4*pl + (kx-ix+1) = base + mF ; always in-bounds
                const float* Aw = A3 + (d * (PCH * 4) + kx + 1);
                int e = beg;
                if ((e & 1) && e < end) {          // peel to 16B-align pair loads
                    const int2 pr = plist[e++];
                    const float w = Aw[pr.x];
                    const float f = F_lane[pr.y];
                    a = fmaf(w, f, a); w_s += w;
                }
                for (; e + 2 <= end; e += 2) {     // pairwise: 1 LDS.128 / 2 entries
                    const int4 pp = *(const int4*)(plist + e);
                    const float w0 = Aw[pp.x];
                    const float w1 = Aw[pp.z];
                    const float f0 = F_lane[pp.y];
                    const float f1 = F_lane[pp.w];
                    a = fmaf(w0, f0, a); w_s += w0;
                    a = fmaf(w1, f1, a); w_s += w1;
                }
                if (e < end) {                     // tail
                    const int2 pr = plist[e];
                    const float w = Aw[pr.x];
                    const float f = F_lane[pr.y];
                    a = fmaf(w, f, a); w_s += w;
                }
            }
            acc[kxi] += a;
            aw[kxi]  += w_s;
        }
        // no trailing sync needed: loop-top __syncthreads fences reuse
    }

    // ---- flush: fire-and-forget REDG, one shot per owned bin ----
#pragma unroll
    for (int kxi = 0; kxi < 8; kxi++) {
        const int k = ky * 16 + 2 * kxi + par;
        float* gb = &g_fsum[(size_t)(b * KK + k) * TROW];
        atomicAdd(gb + lane, acc[kxi]);
        if (lane == 0) atomicAdd(gb + 32, aw[kxi]);
    }

    // ---- fused epilogue: last CTA normalizes, writes out, re-zeroes scratch ----
    __shared__ unsigned s_rank;
    __threadfence();
    __syncthreads();
    if (tid == 0) s_rank = atomicAdd(&g_done, 1u);
    __syncthreads();
    if (s_rank == GRID - 1) {
        __threadfence();
        for (int i = tid; i < BB * KK * CC; i += THREADS) {
            const int c  = i & 31;
            const int bk = i >> 5;
            const float ws = g_fsum[(size_t)bk * TROW + 32];
            const float fs = g_fsum[(size_t)bk * TROW + c];
            const int k = bk & 255, bb2 = bk >> 8;
            out[((size_t)(bb2 * CC) + c) * KK + k] = (ws > 1e-16f) ? fs / ws : 0.f;
        }
        __syncthreads();
        for (int i = tid; i < BB * KK * TROW; i += THREADS) g_fsum[i] = 0.f;
        if (tid == 0) g_done = 0;
    }
}

extern "C" void kernel_launch(void* const* d_in, const int* in_sizes, int n_in,
                              void* d_out, int out_size) {
    const float* feats  = (const float*)d_in[0];
    const float* assoc  = (const float*)d_in[1];
    const int*   idxmap = (const int*)d_in[2];

    static int configured = 0;
    if (!configured) {
        cudaFuncSetAttribute(spix_main, cudaFuncAttributeMaxDynamicSharedMemorySize,
                             SMEM_BYTES);
        configured = 1;
    }
    spix_main<<<GRID, THREADS, SMEM_BYTES>>>(feats, assoc, idxmap, (float*)d_out);
}

// round 14
// speedup vs baseline: 2.1319x; 1.1063x over previous
#include <cuda_runtime.h>
#include <cstdint>

#define BB 4
#define CC 32
#define PP 65536
#define KK 256
#define PCH 1024
#define CHUNKS 2
#define WINPX (PCH * CHUNKS)         // 2048
#define NWIN (PP / WINPX)            // 32
#define GRID (BB * NWIN)             // 128
#define THREADS 1024
#define FSR 36                       // F row stride (floats)
#define TROW 36

#define F_F    (PCH * FSR)           // 36864
#define A3_F   (3 * PCH * 4)         // 12288
#define SMEM_FLOATS (F_F + A3_F + 2 * PCH + KK + KK + 1)
#define SMEM_BYTES  (SMEM_FLOATS * 4)   // ~206 KB -> 1 CTA/SM, 32 warps

__device__ __align__(16) float g_fsum[BB * KK * TROW];  // [b][k][c<32], wsum@32; zero at load
__device__ unsigned g_done;

typedef unsigned long long u64t;

__device__ __forceinline__ void fma2(u64t& d, u64t a, u64t b) {
    asm("fma.rn.f32x2 %0, %1, %2, %0;" : "+l"(d) : "l"(a), "l"(b));
}
__device__ __forceinline__ u64t pack2(float w) {
    u64t r; unsigned u = __float_as_uint(w);
    asm("mov.b64 %0, {%1, %1};" : "=l"(r) : "r"(u));
    return r;
}
__device__ __forceinline__ void unpack2(u64t v, float& lo, float& hi) {
    unsigned a, b;
    asm("mov.b64 {%0, %1}, %2;" : "=r"(a), "=r"(b) : "l"(v));
    lo = __uint_as_float(a); hi = __uint_as_float(b);
}

__global__ __launch_bounds__(THREADS, 1)
void spix_main(const float* __restrict__ feats,
               const float* __restrict__ assoc,
               const int*   __restrict__ idxmap,
               float* __restrict__ out) {
    extern __shared__ float sm[];
    float* F_sh  = sm;                        // [1024][36] pixel-major (32 used)
    float* A3    = sm + F_F;                  // [3][1024][4]: A3[d][p][t] = w[3d+t]
    int2*  plist = (int2*)(A3 + A3_F);        // [1024] {mF = 4*pl - ix, 144*pl}
    int*   cnt   = (int*)(plist + PCH);       // [256]
    int*   offs  = cnt + KK;                  // [257]

    const int b    = blockIdx.x >> 5;
    const int s    = blockIdx.x & 31;
    const int tid  = threadIdx.x;
    const int wid  = tid >> 5;
    const int lane = tid & 31;
    const int grp  = lane >> 4;               // half-warp: entry parity
    const int cl   = lane & 15;               // channel pair (2cl, 2cl+1)
    const int ky   = wid >> 1;
    const int par  = wid & 1;

    // register accumulators: packed channel-pair sums + weight sums, live all kernel
    u64t  acc2[8];
    float aw[8];
#pragma unroll
    for (int i = 0; i < 8; i++) { acc2[i] = 0ull; aw[i] = 0.f; }

    const char* Fb = (const char*)F_sh + 8 * cl;   // + 144*pl per entry

    for (int ch = 0; ch < CHUNKS; ch++) {
        const int p0 = s * WINPX + ch * PCH;

        if (tid < KK) cnt[tid] = 0;
        __syncthreads();   // fences prev-chunk gather before F/A3/plist reuse

        // ---- stage F: thread = pixel; coalesced LDG.32 -> conflict-free STS.128 ----
        {
            const float* src = feats + (size_t)b * CC * PP + p0 + tid;
            float4* dst = (float4*)(F_sh + tid * FSR);
#pragma unroll
            for (int q = 0; q < 8; q++) {
                float4 v;
                v.x = src[(size_t)(4 * q + 0) * PP];
                v.y = src[(size_t)(4 * q + 1) * PP];
                v.z = src[(size_t)(4 * q + 2) * PP];
                v.w = src[(size_t)(4 * q + 3) * PP];
                dst[q] = v;
            }
        }
        // ---- stage A3: thread = pixel; 9 LDG.32 -> 3 STS.128 ----
        {
            const float* src = assoc + (size_t)b * 9 * PP + p0 + tid;
            float w[9];
#pragma unroll
            for (int j = 0; j < 9; j++) w[j] = src[(size_t)j * PP];
#pragma unroll
            for (int d = 0; d < 3; d++)
                ((float4*)A3)[d * PCH + tid] =
                    make_float4(w[3 * d + 0], w[3 * d + 1], w[3 * d + 2], 0.f);
        }

        // ---- count / scan / place (cheap base-bin counting sort) ----
        const int idxA = idxmap[(size_t)b * PP + p0 + tid];
        atomicAdd(&cnt[idxA], 1);
        __syncthreads();

        if (wid == 0) {
            int running = 0;
            for (int g = 0; g < KK / 32; g++) {
                const int v = cnt[g * 32 + lane];
                int incl = v;
#pragma unroll
                for (int d = 1; d < 32; d <<= 1) {
                    int n = __shfl_up_sync(0xffffffffu, incl, d);
                    if (lane >= d) incl += n;
                }
                offs[g * 32 + lane] = running + incl - v;
                running += __shfl_sync(0xffffffffu, incl, 31);
            }
            if (lane == 0) offs[KK] = PCH;
        }
        __syncthreads();
        if (tid < KK) cnt[tid] = offs[tid];
        __syncthreads();
        {
            const int slot = atomicAdd(&cnt[idxA], 1);
            plist[slot] = make_int2(4 * tid - (idxA & 15), 144 * tid);
        }
        __syncthreads();

        // ---- gather: warp owns bins (ky, kx=2*kxi+par); half-warp entry pairing ----
#pragma unroll
        for (int kxi = 0; kxi < 8; kxi++) {
            const int kx = 2 * kxi + par;
            u64t  a2 = 0ull;
            float w_s = 0.f;
            const int xlo = kx > 0  ? kx - 1 : 0;
            const int xhi = kx < 15 ? kx + 1 : 15;
#pragma unroll
            for (int dy = -1; dy <= 1; dy++) {
                const int sy = ky + dy;
                if (sy < 0 || sy > 15) continue;
                const int d = 1 - dy;
                const int beg = offs[sy * 16 + xlo];
                const int end = offs[sy * 16 + xhi + 1];
                const float* Aw = A3 + (d * (PCH * 4) + kx + 1);
                int e = beg;
                for (; e + 2 <= end; e += 2) {        // 2 entries/iter: one per half-warp
                    const int2 pr = plist[e + grp];   // LDS.64, broadcast per half
                    const float w = Aw[pr.x];         // LDS.32 broadcast per half
                    const u64t  f = *(const u64t*)(Fb + pr.y);  // LDS.64 conflict-free
                    fma2(a2, pack2(w), f);            // both channels in one FFMA2
                    w_s += w;
                }
                if (e < end) {                        // odd tail: half 1 neutralized
                    const int  eg = e + grp;
                    const bool vv = eg < end;
                    const int2 pr = plist[vv ? eg : e];
                    float w = Aw[pr.x];               // in-bounds even when !vv
                    if (!vv) w = 0.f;
                    const u64t f = *(const u64t*)(Fb + pr.y);
                    fma2(a2, pack2(w), f);
                    w_s += w;
                }
            }
            // merge into persistent accumulators
            fma2(acc2[kxi], pack2(1.0f), a2);
            aw[kxi] += w_s;
        }
    }

    // ---- flush: merge halves via shfl, fire-and-forget REDG ----
#pragma unroll
    for (int kxi = 0; kxi < 8; kxi++) {
        float lo, hi;
        unpack2(acc2[kxi], lo, hi);
        lo += __shfl_xor_sync(0xffffffffu, lo, 16);
        hi += __shfl_xor_sync(0xffffffffu, hi, 16);
        float awt = aw[kxi] + __shfl_xor_sync(0xffffffffu, aw[kxi], 16);
        const int k = ky * 16 + 2 * kxi + par;
        float* gb = &g_fsum[(size_t)(b * KK + k) * TROW];
        if (lane < 16) {
            atomicAdd(gb + 2 * cl,     lo);
            atomicAdd(gb + 2 * cl + 1, hi);
        } else if (lane == 16) {
            atomicAdd(gb + 32, awt);
        }
    }

    // ---- fused epilogue: last CTA normalizes, writes out, re-zeroes scratch ----
    __shared__ unsigned s_rank;
    __threadfence();
    __syncthreads();
    if (tid == 0) s_rank = atomicAdd(&g_done, 1u);
    __syncthreads();
    if (s_rank == GRID - 1) {
        __threadfence();
        for (int i = tid; i < BB * KK * CC; i += THREADS) {
            const int c  = i & 31;
            const int bk = i >> 5;
            const float ws = g_fsum[(size_t)bk * TROW + 32];
            const float fs = g_fsum[(size_t)bk * TROW + c];
            const int k = bk & 255, bb2 = bk >> 8;
            out[((size_t)(bb2 * CC) + c) * KK + k] = (ws > 1e-16f) ? fs / ws : 0.f;
        }
        __syncthreads();
        for (int i = tid; i < BB * KK * TROW; i += THREADS) g_fsum[i] = 0.f;
        if (tid == 0) g_done = 0;
    }
}

extern "C" void kernel_launch(void* const* d_in, const int* in_sizes, int n_in,
                              void* d_out, int out_size) {
    const float* feats  = (const float*)d_in[0];
    const float* assoc  = (const float*)d_in[1];
    const int*   idxmap = (const int*)d_in[2];

    static int configured = 0;
    if (!configured) {
        cudaFuncSetAttribute(spix_main, cudaFuncAttributeMaxDynamicSharedMemorySize,
                             SMEM_BYTES);
        configured = 1;
    }
    spix_main<<<GRID, THREADS, SMEM_BYTES>>>(feats, assoc, idxmap, (float*)d_out);
}